// round 7
// baseline (speedup 1.0000x reference)
#include <cuda_runtime.h>
#include <cuda_bf16.h>
#include <stdint.h>
#include <stddef.h>
#include <math.h>

#define BATCH 4
#define T     2048
#define D     1024
#define MT    (BATCH * T)   // 8192
#define KE3   3072          // 3*D split-extended K (qkv, scores)

// CTA tile 128x256, 8 warps (2M x 4N), warp tile 64x64, BK=32
#define TM 128
#define TN 256
#define BK 32
#define ASTR 40     // 32 + 8 pad (elems) -> conflict-free ldmatrix
#define B2STR 264   // 256 + 8 pad (elems) for [k][n] V tiles

// ------------------------- device scratch ---------------------------------
__device__ __nv_bfloat16 g_Eext[(size_t)MT * KE3];          // A-role [hi|lo|hi]
__device__ __nv_bfloat16 g_WText[(size_t)3 * D * KE3];      // [n][k] B-role [hi|hi|lo]
__device__ __nv_bfloat16 g_Qext[(size_t)MT * KE3];          // A-role [hi|lo|hi]
__device__ __nv_bfloat16 g_Kext[(size_t)MT * KE3];          // B-role [hi|hi|lo]
__device__ __nv_bfloat16 g_Vext[(size_t)BATCH * 3 * T * D]; // [b][seg][t][d], seg=[hi,hi,lo]
__device__ float         g_S[(size_t)BATCH * T * T];        // fp32 scores
__device__ __nv_bfloat16 g_Sext[(size_t)BATCH * T * 3 * T]; // A-role [hi|lo|hi] along keys

// ------------------------- helpers ------------------------------------
__device__ __forceinline__ uint32_t smem_u32(const void* p) {
    uint32_t a;
    asm("{ .reg .u64 t; cvta.to.shared.u64 t, %1; cvt.u32.u64 %0, t; }" : "=r"(a) : "l"(p));
    return a;
}
__device__ __forceinline__ void ldsm_x4(uint32_t& r0, uint32_t& r1, uint32_t& r2, uint32_t& r3,
                                        uint32_t addr) {
    asm volatile("ldmatrix.sync.aligned.m8n8.x4.shared.b16 {%0,%1,%2,%3}, [%4];"
                 : "=r"(r0), "=r"(r1), "=r"(r2), "=r"(r3) : "r"(addr));
}
__device__ __forceinline__ void ldsm_x4_t(uint32_t& r0, uint32_t& r1, uint32_t& r2, uint32_t& r3,
                                          uint32_t addr) {
    asm volatile("ldmatrix.sync.aligned.m8n8.x4.trans.shared.b16 {%0,%1,%2,%3}, [%4];"
                 : "=r"(r0), "=r"(r1), "=r"(r2), "=r"(r3) : "r"(addr));
}
__device__ __forceinline__ void mma_bf16(float* c, const uint32_t* a, const uint32_t* b) {
    asm volatile("mma.sync.aligned.m16n8k16.row.col.f32.bf16.bf16.f32 "
                 "{%0,%1,%2,%3}, {%4,%5,%6,%7}, {%8,%9}, {%0,%1,%2,%3};"
                 : "+f"(c[0]), "+f"(c[1]), "+f"(c[2]), "+f"(c[3])
                 : "r"(a[0]), "r"(a[1]), "r"(a[2]), "r"(a[3]), "r"(b[0]), "r"(b[1]));
}
__device__ __forceinline__ void bsplit(float x, __nv_bfloat16& h, __nv_bfloat16& l) {
    h = __float2bfloat16(x);
    l = __float2bfloat16(x - __bfloat162float(h));
}
__device__ __forceinline__ __nv_bfloat162 mk2(__nv_bfloat16 a, __nv_bfloat16 b) {
    __nv_bfloat162 v; v.x = a; v.y = b; return v;
}

// ------------------------- conversion kernels ------------------------------
__global__ __launch_bounds__(256)
void convE_kernel(const float* __restrict__ E) {
    int idx = blockIdx.x * 256 + threadIdx.x;   // over MT*D
    int row = idx >> 10, k = idx & 1023;
    __nv_bfloat16 h, l;
    bsplit(E[idx], h, l);
    __nv_bfloat16* p = g_Eext + (size_t)row * KE3;
    p[k] = h; p[D + k] = l; p[2 * D + k] = h;   // A-role [hi, lo, hi]
}

__global__ __launch_bounds__(256)
void convW_kernel(const float* __restrict__ Wk, const float* __restrict__ Wq,
                  const float* __restrict__ Wv) {
    const float* W = (blockIdx.z == 0) ? Wk : (blockIdx.z == 1) ? Wq : Wv;
    __nv_bfloat16* dst = g_WText + (size_t)blockIdx.z * D * KE3;
    __shared__ float tsm[32][33];
    int n0 = blockIdx.x * 32, k0 = blockIdx.y * 32;
    int tx = threadIdx.x, ty = threadIdx.y;
    #pragma unroll
    for (int i = 0; i < 4; i++)
        tsm[ty + 8 * i][tx] = W[(size_t)(k0 + ty + 8 * i) * D + n0 + tx];
    __syncthreads();
    #pragma unroll
    for (int i = 0; i < 4; i++) {
        int n = n0 + ty + 8 * i, k = k0 + tx;
        __nv_bfloat16 h, l;
        bsplit(tsm[tx][ty + 8 * i], h, l);       // = W[k][n]
        __nv_bfloat16* p = dst + (size_t)n * KE3;
        p[k] = h; p[D + k] = h; p[2 * D + k] = l;  // B-role [hi, hi, lo]
    }
}

// ------------------------- unified mma.sync GEMM ---------------------------
// MODE 0: qkv   out = E_ext @ WText[z]^T                grid (4, 64, 3)
// MODE 1: score S[b] = Q_ext @ K_ext^T (/32, causal)    grid (8, 16, 4)
// MODE 2: av    O[b] = S_ext @ V_ext (trans-B, bounded) grid (4, 16, 4)
template <int MODE>
__global__ __launch_bounds__(256)
void gemm_mma(float* __restrict__ outp) {
    __shared__ __nv_bfloat16 As[TM * ASTR];     // 5120 elems = 10240 B
    __shared__ __nv_bfloat16 Bs[TN * ASTR];     // 10240 elems = 20480 B (>= 32*B2STR)

    const int tid = threadIdx.x;
    const int wid = tid >> 5, l = tid & 31;
    const int wm = wid & 1, wn = wid >> 1;          // 2(M) x 4(N) warp grid
    const int warpM = wm * 64, warpN = wn * 64;     // warp tile 64x64
    const int bx = blockIdx.x, by = blockIdx.y, bz = blockIdx.z;
    const int mBase = by * TM, nBase = bx * TN;

    const __nv_bfloat16 *Ag, *Bg;
    int ldk, nIter, nJ;
    if (MODE == 0) {
        Ag = g_Eext; Bg = g_WText + (size_t)bz * D * KE3;
        ldk = KE3; nJ = KE3 / BK; nIter = nJ;
    } else if (MODE == 1) {
        if (nBase > mBase + TM - 1) return;         // fully above diagonal
        Ag = g_Qext + (size_t)bz * T * KE3;
        Bg = g_Kext + (size_t)bz * T * KE3;
        ldk = KE3; nJ = KE3 / BK; nIter = nJ;
    } else {
        Ag = g_Sext + (size_t)bz * T * (3 * T);
        Bg = g_Vext + (size_t)bz * (3 * T) * D;
        ldk = 3 * T;
        nJ = ((by + 1) * TM) / BK;                  // causal K bound per segment
        nIter = 3 * nJ;
    }

    float c[4][8][4] = {};
    uint4 pa[2], pb[4];

    // ---- global loaders (into registers) ----
    const int aRow = tid >> 2;                 // 0..63
    const int aKc  = (tid & 3) * 8;            // 0,8,16,24
    const int vRow = tid >> 5;                 // 0..7 (mode2 B k rows)
    const int vNc  = (tid & 31) * 8;           // 0..248

    auto kOff = [&](int it) -> int {
        if (MODE == 2) { int s = it / nJ; return s * T + (it - s * nJ) * BK; }
        return it * BK;
    };
    auto loadG = [&](int ko) {
        pa[0] = *(const uint4*)(Ag + (size_t)(mBase + aRow) * ldk + ko + aKc);
        pa[1] = *(const uint4*)(Ag + (size_t)(mBase + aRow + 64) * ldk + ko + aKc);
        if (MODE != 2) {
            #pragma unroll
            for (int g = 0; g < 4; g++)
                pb[g] = *(const uint4*)(Bg + (size_t)(nBase + aRow + g * 64) * ldk + ko + aKc);
        } else {
            #pragma unroll
            for (int g = 0; g < 4; g++)
                pb[g] = *(const uint4*)(Bg + (size_t)(ko + vRow + g * 8) * D + nBase + vNc);
        }
    };
    auto stsAll = [&]() {
        *(uint4*)&As[aRow * ASTR + aKc]        = pa[0];
        *(uint4*)&As[(aRow + 64) * ASTR + aKc] = pa[1];
        if (MODE != 2) {
            #pragma unroll
            for (int g = 0; g < 4; g++)
                *(uint4*)&Bs[(aRow + g * 64) * ASTR + aKc] = pb[g];
        } else {
            #pragma unroll
            for (int g = 0; g < 4; g++)
                *(uint4*)&Bs[(vRow + g * 8) * B2STR + vNc] = pb[g];
        }
    };

    const uint32_t AsU = smem_u32(As), BsU = smem_u32(Bs);
    // lane-invariant ldmatrix addressing pieces
    const int aLR = (l & 15), aLC = (l >> 4) * 8;                       // A rows/k
    const int bLR = (l >> 4) * 8 + (l & 7), bLC = ((l >> 3) & 1) * 8;   // B[n][k]
    const int vLR = ((l >> 3) & 1) * 8 + (l & 7), vLC = (l >> 4) * 8;   // B[k][n] trans

    loadG(kOff(0));

    for (int it = 0; it < nIter; it++) {
        stsAll();
        __syncthreads();
        if (it + 1 < nIter) loadG(kOff(it + 1));

        #pragma unroll
        for (int ks = 0; ks < 2; ks++) {
            uint32_t a[4][4], b[8][2];
            #pragma unroll
            for (int mi = 0; mi < 4; mi++)
                ldsm_x4(a[mi][0], a[mi][1], a[mi][2], a[mi][3],
                        AsU + ((warpM + mi * 16 + aLR) * ASTR + ks * 16 + aLC) * 2);
            if (MODE != 2) {
                #pragma unroll
                for (int n2 = 0; n2 < 8; n2 += 2)
                    ldsm_x4(b[n2][0], b[n2][1], b[n2 + 1][0], b[n2 + 1][1],
                            BsU + ((warpN + n2 * 8 + bLR) * ASTR + ks * 16 + bLC) * 2);
            } else {
                #pragma unroll
                for (int n2 = 0; n2 < 8; n2 += 2)
                    ldsm_x4_t(b[n2][0], b[n2][1], b[n2 + 1][0], b[n2 + 1][1],
                              BsU + ((ks * 16 + vLR) * B2STR + warpN + n2 * 8 + vLC) * 2);
            }
            #pragma unroll
            for (int mi = 0; mi < 4; mi++)
                #pragma unroll
                for (int ni = 0; ni < 8; ni++)
                    mma_bf16(c[mi][ni], a[mi], b[ni]);
        }
        __syncthreads();
    }

    // ---- epilogue (direct from accumulators) ----
    const int l4 = l >> 2, l2 = (l & 3) * 2;
    #pragma unroll
    for (int mi = 0; mi < 4; mi++) {
        #pragma unroll
        for (int ni = 0; ni < 8; ni++) {
            const int n = nBase + warpN + ni * 8 + l2;
            #pragma unroll
            for (int half = 0; half < 2; half++) {
                const int m = mBase + warpM + mi * 16 + l4 + half * 8;
                float v0 = c[mi][ni][half * 2 + 0];
                float v1 = c[mi][ni][half * 2 + 1];
                if (MODE == 0) {
                    __nv_bfloat16 h0, l0, h1, l1;
                    bsplit(v0, h0, l0); bsplit(v1, h1, l1);
                    if (bz == 1) {        // Q: A-role [hi, lo, hi]
                        __nv_bfloat16* p = g_Qext + (size_t)m * KE3;
                        *(__nv_bfloat162*)(p + n)         = mk2(h0, h1);
                        *(__nv_bfloat162*)(p + D + n)     = mk2(l0, l1);
                        *(__nv_bfloat162*)(p + 2 * D + n) = mk2(h0, h1);
                    } else if (bz == 0) { // K: B-role [hi, hi, lo]
                        __nv_bfloat16* p = g_Kext + (size_t)m * KE3;
                        *(__nv_bfloat162*)(p + n)         = mk2(h0, h1);
                        *(__nv_bfloat162*)(p + D + n)     = mk2(h0, h1);
                        *(__nv_bfloat162*)(p + 2 * D + n) = mk2(l0, l1);
                    } else {              // V: [b][seg][t][d], segs [hi, hi, lo]
                        int bb = m >> 11, t = m & (T - 1);
                        __nv_bfloat16* p = g_Vext + (size_t)bb * 3 * T * D;
                        *(__nv_bfloat162*)(p + (size_t)t * D + n)           = mk2(h0, h1);
                        *(__nv_bfloat162*)(p + (size_t)(T + t) * D + n)     = mk2(h0, h1);
                        *(__nv_bfloat162*)(p + (size_t)(2 * T + t) * D + n) = mk2(l0, l1);
                    }
                } else if (MODE == 1) {
                    float s0 = (n     > m) ? -INFINITY : v0 * 0.03125f;
                    float s1 = (n + 1 > m) ? -INFINITY : v1 * 0.03125f;
                    float* p = g_S + (size_t)bz * T * T + (size_t)m * T + n;
                    p[0] = s0; p[1] = s1;
                } else {
                    float* p = outp + (size_t)bz * T * D + (size_t)m * D + n;
                    p[0] = rintf(v0 * 10000.0f) * 1.0e-4f;
                    p[1] = rintf(v1 * 10000.0f) * 1.0e-4f;
                }
            }
        }
    }
}

// ------------------------- softmax -> split bf16 ---------------------------
__global__ __launch_bounds__(256)
void softmax_kernel() {
    const int r = blockIdx.x;
    const int b = r >> 11, t = r & (T - 1);
    float* row = g_S + (size_t)b * T * T + (size_t)t * T;
    __nv_bfloat16* orow = g_Sext + ((size_t)b * T + t) * (3 * T);
    const int L = ((t >> 7) + 1) << 7;   // ceil to 128-tile

    __shared__ float red[256];
    const int tid = threadIdx.x;

    float m = -INFINITY;
    for (int j = tid; j < L; j += 256) m = fmaxf(m, row[j]);
    red[tid] = m;
    __syncthreads();
    #pragma unroll
    for (int s = 128; s > 0; s >>= 1) {
        if (tid < s) red[tid] = fmaxf(red[tid], red[tid + s]);
        __syncthreads();
    }
    m = red[0];
    __syncthreads();

    float sum = 0.0f;
    for (int j = tid; j < L; j += 256) {
        float e = __expf(row[j] - m);   // exp(-inf)=0 handles the causal mask
        row[j] = e;
        sum += e;
    }
    red[tid] = sum;
    __syncthreads();
    #pragma unroll
    for (int s = 128; s > 0; s >>= 1) {
        if (tid < s) red[tid] += red[tid + s];
        __syncthreads();
    }
    const float inv = 1.0f / red[0];
    __syncthreads();

    for (int j = tid; j < L; j += 256) {
        float w = row[j] * inv;
        __nv_bfloat16 h, l;
        bsplit(w, h, l);
        orow[j] = h; orow[T + j] = l; orow[2 * T + j] = h;   // A-role [hi, lo, hi]
    }
}

// ---------------------------------------------------------------------------
extern "C" void kernel_launch(void* const* d_in, const int* in_sizes, int n_in,
                              void* d_out, int out_size) {
    const float* E  = (const float*)d_in[0];
    const float* Wk = (const float*)d_in[1];
    const float* Wq = (const float*)d_in[2];
    const float* Wv = (const float*)d_in[3];
    float* O = (float*)d_out;

    convE_kernel<<<(MT * D) / 256, 256>>>(E);
    convW_kernel<<<dim3(32, 32, 3), dim3(32, 8)>>>(Wk, Wq, Wv);
    gemm_mma<0><<<dim3(D / TN, MT / TM, 3), 256>>>(O);
    gemm_mma<1><<<dim3(T / TN, T / TM, BATCH), 256>>>(O);
    softmax_kernel<<<MT, 256>>>();
    gemm_mma<2><<<dim3(D / TN, T / TM, BATCH), 256>>>(O);
}